// round 14
// baseline (speedup 1.0000x reference)
#include <cuda_runtime.h>
#include <cuda_bf16.h>
#include <cuda_fp16.h>
#include <math.h>
#include <stdint.h>

#define N_NODES 100000
#define N_EDGES 3200000
#define NFEAT   512
#define HIDDEN  256
#define NCLASS  64
#define KITER   10
#define M_PAD   100096   // 782 * 128
#define NB      ((N_NODES + 255) / 256)   // 391
#define EB      ((N_EDGES + 255) / 256)
#define HSZ     ((size_t)N_NODES * NCLASS)

// ---------------- device scratch (no allocations allowed) ----------------
__device__ int    g_ecnt[N_NODES];
__device__ int    g_pos[N_NODES];
__device__ int    g_off[N_NODES + 1];
__device__ int    g_bsum[NB];
__device__ int    g_boff[NB];
__device__ float  g_dinv[N_NODES];
__device__ float2 g_edge[N_EDGES];
__device__ __align__(256) __nv_bfloat16 g_B1[(size_t)HIDDEN * 1024];  // [256][1024]: W1h|W1l
__device__ __align__(256) __nv_bfloat16 g_B2[(size_t)NCLASS * 512];   // [64][512]:  W2h|W2l
__device__ __align__(256) __half g_hk[(size_t)(KITER + 1) * HSZ];     // fp16 prop states h_0..h_10

// ---------------- PTX helpers (baseline PTX only: sm_80-era) ----------------
__device__ __forceinline__ uint32_t smem_u32(const void* p) {
    uint32_t a;
    asm("{ .reg .u64 t; cvta.to.shared.u64 t, %1; cvt.u32.u64 %0, t; }" : "=r"(a) : "l"(p));
    return a;
}
#define CP_ASYNC16(dst, src) \
    asm volatile("cp.async.cg.shared.global [%0], [%1], 16;" :: "r"(dst), "l"(src) : "memory")
#define CP_COMMIT() asm volatile("cp.async.commit_group;" ::: "memory")
#define CP_WAIT1()  asm volatile("cp.async.wait_group 1;" ::: "memory")
#define CP_WAIT0()  asm volatile("cp.async.wait_group 0;" ::: "memory")

#define LDSM_X4(r0, r1, r2, r3, addr)                                         \
    asm volatile("ldmatrix.sync.aligned.m8n8.x4.shared.b16 {%0,%1,%2,%3},[%4];" \
        : "=r"(r0), "=r"(r1), "=r"(r2), "=r"(r3) : "r"(addr))

#define MMA16816(d, a, b)                                                     \
    asm volatile("mma.sync.aligned.m16n8k16.row.col.f32.bf16.bf16.f32 "       \
        "{%0,%1,%2,%3},{%4,%5,%6,%7},{%8,%9},{%0,%1,%2,%3};"                  \
        : "+f"((d)[0]), "+f"((d)[1]), "+f"((d)[2]), "+f"((d)[3])              \
        : "r"((a)[0]), "r"((a)[1]), "r"((a)[2]), "r"((a)[3]),                 \
          "r"((b)[0]), "r"((b)[1]))

// smem layout for fused kernel
#define ST1      49152
#define XH_OFF   98304
#define XL_OFF   106496
#define MIDH_OFF 0
#define MIDL_OFF 65536
#define B2_OFF   131072
#define SMEMF    147456

// per-block edge_index dtype detection: warp 0 ballots over the high words
// of the first 64 int64 candidates (indices < 2^31 => all zero iff int64).
__device__ __forceinline__ int block_is64(const int* __restrict__ e32, int* s64) {
    if (threadIdx.x < 32) {
        int v = e32[2 * threadIdx.x + 1] | e32[2 * (threadIdx.x + 32) + 1];
        unsigned nz = __ballot_sync(0xFFFFFFFFu, v != 0);
        if (threadIdx.x == 0) *s64 = (nz == 0u);
    }
    __syncthreads();
    return *s64;
}

// ---------------- graph preprocessing ----------------
__global__ void k_init() {
    int i = blockIdx.x * blockDim.x + threadIdx.x;
    if (i < N_NODES) g_ecnt[i] = 0;
}

// count in-degree: only needs the col (target) half of edge_index
__global__ void k_count(const void* __restrict__ ei) {
    __shared__ int s64;
    int is64 = block_is64((const int*)ei, &s64);
    int e = blockIdx.x * blockDim.x + threadIdx.x;
    if (e >= N_EDGES) return;
    int c;
    if (is64) c = (int)((const long long*)ei)[(size_t)N_EDGES + e];
    else      c = ((const int*)ei)[(size_t)N_EDGES + e];
    if ((unsigned)c < N_NODES) atomicAdd(&g_ecnt[c], 1);
}

// per-256-block sums of g_ecnt
__global__ void k_bsum() {
    __shared__ int ws[8];
    int b = blockIdx.x, t = threadIdx.x;
    int i = b * 256 + t;
    int v = (i < N_NODES) ? g_ecnt[i] : 0;
    #pragma unroll
    for (int o = 16; o > 0; o >>= 1) v += __shfl_xor_sync(0xFFFFFFFFu, v, o);
    if ((t & 31) == 0) ws[t >> 5] = v;
    __syncthreads();
    if (t == 0) {
        int s = 0;
        #pragma unroll
        for (int j = 0; j < 8; j++) s += ws[j];
        g_bsum[b] = s;
    }
}

// exclusive scan of the 391 block sums (one block)
__global__ void k_scanb() {
    __shared__ int wsum[16];
    int t = threadIdx.x, lane = t & 31, w = t >> 5;
    int v = (t < NB) ? g_bsum[t] : 0;
    int x = v;
    #pragma unroll
    for (int o = 1; o < 32; o <<= 1) {
        int u = __shfl_up_sync(0xFFFFFFFFu, x, o);
        if (lane >= o) x += u;
    }
    if (lane == 31) wsum[w] = x;
    __syncthreads();
    if (t == 0) {
        int run = 0;
        #pragma unroll
        for (int j = 0; j < 16; j++) { int tmp = wsum[j]; wsum[j] = run; run += tmp; }
    }
    __syncthreads();
    if (t < NB) g_boff[t] = wsum[w] + x - v;
}

// final offsets + dinv + pos=0 (fused)
__global__ void k_offsets() {
    __shared__ int wsum[8];
    int b = blockIdx.x, t = threadIdx.x, lane = t & 31, w = t >> 5;
    int i = b * 256 + t;
    int v = (i < N_NODES) ? g_ecnt[i] : 0;
    int x = v;
    #pragma unroll
    for (int o = 1; o < 32; o <<= 1) {
        int u = __shfl_up_sync(0xFFFFFFFFu, x, o);
        if (lane >= o) x += u;
    }
    if (lane == 31) wsum[w] = x;
    __syncthreads();
    if (t == 0) {
        int run = 0;
        #pragma unroll
        for (int j = 0; j < 8; j++) { int tmp = wsum[j]; wsum[j] = run; run += tmp; }
    }
    __syncthreads();
    int off = g_boff[b] + wsum[w] + x - v;
    if (i < N_NODES) {
        g_off[i] = off;
        g_pos[i] = 0;
        g_dinv[i] = rsqrtf((float)(v + 1));
        if (i == N_NODES - 1) g_off[N_NODES] = off + v;
    }
}

__global__ void k_scatter(const void* __restrict__ ei) {
    __shared__ int s64;
    int is64 = block_is64((const int*)ei, &s64);
    int e = blockIdx.x * blockDim.x + threadIdx.x;
    if (e >= N_EDGES) return;
    int r, c;
    if (is64) {
        const long long* p = (const long long*)ei;
        r = (int)p[e];
        c = (int)p[(size_t)N_EDGES + e];
    } else {
        const int* p = (const int*)ei;
        r = p[e];
        c = p[(size_t)N_EDGES + e];
    }
    if ((unsigned)r >= N_NODES || (unsigned)c >= N_NODES) return;
    int p = g_off[c] + atomicAdd(&g_pos[c], 1);
    if (p >= N_EDGES) return;
    float w = g_dinv[r] * g_dinv[c];
    g_edge[p] = make_float2(__int_as_float(r), w);
}

// ---------------- weight split preprocessing (both weights, one kernel) -----
__global__ void k_split_w(const float* __restrict__ W1, const float* __restrict__ W2) {
    int i = blockIdx.x * blockDim.x + threadIdx.x;
    if (i < HIDDEN * 1024) {
        int n = i >> 10, k = i & 1023;
        int kk = k & 511;
        bool lo = k >= 512;
        float w = W1[(size_t)kk * HIDDEN + n];
        __nv_bfloat16 h = __float2bfloat16(w);
        g_B1[i] = lo ? __float2bfloat16(w - __bfloat162float(h)) : h;
    } else {
        int j = i - HIDDEN * 1024;
        if (j < NCLASS * 512) {
            int n = j >> 9, k = j & 511;
            int kk = k & 255;
            bool lo = k >= 256;
            float w = W2[(size_t)kk * NCLASS + n];
            __nv_bfloat16 h = __float2bfloat16(w);
            g_B2[j] = lo ? __float2bfloat16(w - __bfloat162float(h)) : h;
        }
    }
}

// ---------------- fused MLP: h0 = relu(x@W1+b1)@W2+b2 (fp16 out) ------------
__global__ __launch_bounds__(256) void k_fused(const float* __restrict__ x,
                                               const float* __restrict__ b1,
                                               const float* __restrict__ b2) {
    extern __shared__ char sm[];
    uint32_t su = smem_u32(sm);
    int tid = threadIdx.x, lane = tid & 31, wid = tid >> 5;
    int rowbase = blockIdx.x * 128;

    // ================= phase 1 =================
    int warp_m = wid & 1, warp_n = wid >> 1;
    float acc[4][8][4] = {};

    auto load1 = [&](int c, uint32_t bufu) {
        #pragma unroll
        for (int g0 = 0; g0 < 1024; g0 += 256) {
            int g = g0 + tid;
            int r = g >> 3, gc = g & 7;
            int rs = rowbase + r; if (rs >= N_NODES) rs = N_NODES - 1;
            const void* src = x + (size_t)rs * NFEAT + c * 32 + gc * 4;
            CP_ASYNC16(bufu + r * 128 + ((gc ^ (r & 7)) << 4), src);
        }
        #pragma unroll
        for (int g0 = 0; g0 < 1024; g0 += 256) {
            int g = g0 + tid;
            int n = g >> 2, gc = g & 3;
            uint32_t d = n * 64 + ((gc ^ (n & 3)) << 4);
            const void* sh = g_B1 + (size_t)n * 1024 + c * 32 + gc * 8;
            CP_ASYNC16(bufu + 16384 + d, sh);
            const void* sl = g_B1 + (size_t)n * 1024 + 512 + c * 32 + gc * 8;
            CP_ASYNC16(bufu + 32768 + d, sl);
        }
    };

    auto convert1 = [&](int bufoff) {
        int row = tid >> 1, half = tid & 1;
        const char* xs = sm + bufoff;
        float4 f[4];
        #pragma unroll
        for (int g = 0; g < 4; g++) {
            int ig = half * 4 + g;
            f[g] = *(const float4*)(xs + row * 128 + ((ig ^ (row & 7)) << 4));
        }
        #pragma unroll
        for (int j = 0; j < 2; j++) {
            float vv[8] = { f[2*j].x, f[2*j].y, f[2*j].z, f[2*j].w,
                            f[2*j+1].x, f[2*j+1].y, f[2*j+1].z, f[2*j+1].w };
            uint32_t hp[4], lp[4];
            #pragma unroll
            for (int q = 0; q < 4; q++) {
                __nv_bfloat162 hh = __floats2bfloat162_rn(vv[2*q], vv[2*q+1]);
                __nv_bfloat162 ll = __floats2bfloat162_rn(vv[2*q]   - __bfloat162float(hh.x),
                                                          vv[2*q+1] - __bfloat162float(hh.y));
                hp[q] = *(uint32_t*)&hh;
                lp[q] = *(uint32_t*)&ll;
            }
            int og = half * 2 + j;
            int phys = og ^ (row & 3);
            *(uint4*)(sm + XH_OFF + row * 64 + phys * 16) = make_uint4(hp[0], hp[1], hp[2], hp[3]);
            *(uint4*)(sm + XL_OFF + row * 64 + phys * 16) = make_uint4(lp[0], lp[1], lp[2], lp[3]);
        }
    };

    auto compute1 = [&](uint32_t bufu) {
        uint32_t Bh = bufu + 16384, Bl = bufu + 32768;
        uint32_t XHu = su + XH_OFF, XLu = su + XL_OFF;
        #pragma unroll
        for (int kk = 0; kk < 2; kk++) {
            uint32_t aH[4][4], aL[4][4], bH[8][2], bL[8][2];
            int kbA = kk * 32 + ((lane >> 4) << 4);
            #pragma unroll
            for (int mi = 0; mi < 4; mi++) {
                int row = warp_m * 64 + mi * 16 + (lane & 15);
                uint32_t ad = XHu + row * 64 + ((((kbA >> 4) ^ (row & 3)) << 4) | (kbA & 15));
                LDSM_X4(aH[mi][0], aH[mi][1], aH[mi][2], aH[mi][3], ad);
            }
            int kbB = kk * 32 + ((lane & 8) ? 16 : 0);
            #pragma unroll
            for (int nj = 0; nj < 4; nj++) {
                int n = warp_n * 64 + nj * 16 + (lane & 7) + ((lane & 16) ? 8 : 0);
                uint32_t off = n * 64 + ((((kbB >> 4) ^ (n & 3)) << 4) | (kbB & 15));
                uint32_t r0, r1, r2, r3;
                LDSM_X4(r0, r1, r2, r3, Bh + off);
                bH[nj * 2][0] = r0;     bH[nj * 2][1] = r1;
                bH[nj * 2 + 1][0] = r2; bH[nj * 2 + 1][1] = r3;
            }
            #pragma unroll
            for (int mi = 0; mi < 4; mi++)
                #pragma unroll
                for (int ni = 0; ni < 8; ni++)
                    MMA16816(acc[mi][ni], aH[mi], bH[ni]);
            #pragma unroll
            for (int nj = 0; nj < 4; nj++) {
                int n = warp_n * 64 + nj * 16 + (lane & 7) + ((lane & 16) ? 8 : 0);
                uint32_t off = n * 64 + ((((kbB >> 4) ^ (n & 3)) << 4) | (kbB & 15));
                uint32_t r0, r1, r2, r3;
                LDSM_X4(r0, r1, r2, r3, Bl + off);
                bL[nj * 2][0] = r0;     bL[nj * 2][1] = r1;
                bL[nj * 2 + 1][0] = r2; bL[nj * 2 + 1][1] = r3;
            }
            #pragma unroll
            for (int mi = 0; mi < 4; mi++)
                #pragma unroll
                for (int ni = 0; ni < 8; ni++)
                    MMA16816(acc[mi][ni], aH[mi], bL[ni]);
            #pragma unroll
            for (int mi = 0; mi < 4; mi++) {
                int row = warp_m * 64 + mi * 16 + (lane & 15);
                uint32_t ad = XLu + row * 64 + ((((kbA >> 4) ^ (row & 3)) << 4) | (kbA & 15));
                LDSM_X4(aL[mi][0], aL[mi][1], aL[mi][2], aL[mi][3], ad);
            }
            #pragma unroll
            for (int mi = 0; mi < 4; mi++)
                #pragma unroll
                for (int ni = 0; ni < 8; ni++)
                    MMA16816(acc[mi][ni], aL[mi], bH[ni]);
        }
    };

    load1(0, su);
    CP_COMMIT();
    for (int c = 0; c < 16; c++) {
        uint32_t buf = su + (c & 1) * ST1;
        if (c + 1 < 16) {
            load1(c + 1, su + ((c + 1) & 1) * ST1);
            CP_COMMIT();
            CP_WAIT1();
        } else {
            CP_WAIT0();
        }
        __syncthreads();
        convert1((c & 1) * ST1);
        __syncthreads();
        compute1(buf);
        __syncthreads();
    }

    #pragma unroll
    for (int mi = 0; mi < 4; mi++) {
        #pragma unroll
        for (int h = 0; h < 2; h++) {
            int r = warp_m * 64 + mi * 16 + (lane >> 2) + h * 8;
            #pragma unroll
            for (int ni = 0; ni < 8; ni++) {
                int cg = warp_n * 64 + ni * 8 + (lane & 3) * 2;
                float v0 = acc[mi][ni][2 * h]     + __ldg(&b1[cg]);
                float v1 = acc[mi][ni][2 * h + 1] + __ldg(&b1[cg + 1]);
                v0 = fmaxf(v0, 0.f);
                v1 = fmaxf(v1, 0.f);
                __nv_bfloat162 hh = __floats2bfloat162_rn(v0, v1);
                __nv_bfloat162 ll = __floats2bfloat162_rn(v0 - __bfloat162float(hh.x),
                                                          v1 - __bfloat162float(hh.y));
                int blk = cg >> 6, kb = (cg & 63) * 2;
                uint32_t off = blk * 16384 + r * 128 + ((((kb >> 4) ^ (r & 7)) << 4) | (kb & 15));
                *(uint32_t*)(sm + MIDH_OFF + off) = *(uint32_t*)&hh;
                *(uint32_t*)(sm + MIDL_OFF + off) = *(uint32_t*)&ll;
            }
        }
    }
    __syncthreads();

    // ================= phase 2 =================
    int warp_m2 = wid >> 1, warp_n2 = wid & 1;
    float acc2[2][4][4] = {};

    auto loadB2 = [&](int s, uint32_t bufu) {
        int kc = (s < 8) ? s : (s - 8);
        #pragma unroll
        for (int g0 = 0; g0 < 512; g0 += 256) {
            int g = g0 + tid;
            int n = g >> 3, gc = g & 7;
            const void* src = g_B2 + (size_t)n * 512 + kc * 64 + gc * 8;
            CP_ASYNC16(bufu + n * 128 + ((gc ^ (n & 7)) << 4), src);
        }
    };

    auto compute2 = [&](int s, uint32_t bufu) {
        uint32_t Au = su + ((s < 8) ? MIDH_OFF : MIDL_OFF) + (s & 3) * 16384;
        #pragma unroll
        for (int kk = 0; kk < 4; kk++) {
            uint32_t a[2][4], b[4][2];
            int kbA = kk * 32 + ((lane >> 4) << 4);
            #pragma unroll
            for (int mi = 0; mi < 2; mi++) {
                int row = warp_m2 * 32 + mi * 16 + (lane & 15);
                uint32_t ad = Au + row * 128 + ((((kbA >> 4) ^ (row & 7)) << 4) | (kbA & 15));
                LDSM_X4(a[mi][0], a[mi][1], a[mi][2], a[mi][3], ad);
            }
            int kbB = kk * 32 + ((lane & 8) ? 16 : 0);
            #pragma unroll
            for (int nj = 0; nj < 2; nj++) {
                int n = warp_n2 * 32 + nj * 16 + (lane & 7) + ((lane & 16) ? 8 : 0);
                uint32_t off = n * 128 + ((((kbB >> 4) ^ (n & 7)) << 4) | (kbB & 15));
                uint32_t r0, r1, r2, r3;
                LDSM_X4(r0, r1, r2, r3, bufu + off);
                b[nj * 2][0] = r0;     b[nj * 2][1] = r1;
                b[nj * 2 + 1][0] = r2; b[nj * 2 + 1][1] = r3;
            }
            #pragma unroll
            for (int mi = 0; mi < 2; mi++)
                #pragma unroll
                for (int ni = 0; ni < 4; ni++)
                    MMA16816(acc2[mi][ni], a[mi], b[ni]);
        }
    };

    loadB2(0, su + B2_OFF);
    CP_COMMIT();
    for (int s = 0; s < 12; s++) {
        if (s + 1 < 12) {
            loadB2(s + 1, su + B2_OFF + ((s + 1) & 1) * 8192);
            CP_COMMIT();
            CP_WAIT1();
        } else {
            CP_WAIT0();
        }
        __syncthreads();
        compute2(s, su + B2_OFF + (s & 1) * 8192);
        __syncthreads();
    }

    #pragma unroll
    for (int mi = 0; mi < 2; mi++) {
        #pragma unroll
        for (int h = 0; h < 2; h++) {
            int r = rowbase + warp_m2 * 32 + mi * 16 + (lane >> 2) + h * 8;
            if (r < N_NODES) {
                #pragma unroll
                for (int ni = 0; ni < 4; ni++) {
                    int col = warp_n2 * 32 + ni * 8 + (lane & 3) * 2;
                    float v0 = acc2[mi][ni][2 * h]     + __ldg(&b2[col]);
                    float v1 = acc2[mi][ni][2 * h + 1] + __ldg(&b2[col + 1]);
                    *(__half2*)&g_hk[(size_t)r * NCLASS + col] = __floats2half2_rn(v0, v1);
                }
            }
        }
    }
}

// ---------------- propagation: h_{k+1} = Ahat @ h_k (fp16 states) -----------
__global__ __launch_bounds__(256) void k_prop(int k) {
    int t = blockIdx.x * blockDim.x + threadIdx.x;
    int c = t >> 5, lane = t & 31;
    if (c >= N_NODES) return;
    const __half2* hin2 = (const __half2*)(g_hk + (size_t)k * HSZ);
    __half2*       hout2 = (__half2*)(g_hk + (size_t)(k + 1) * HSZ);

    float dc = g_dinv[c];
    float sw = dc * dc;
    float2 v = __half22float2(hin2[(size_t)c * 32 + lane]);
    float2 acc;
    acc.x = sw * v.x;
    acc.y = sw * v.y;

    int b = g_off[c], e = g_off[c + 1];
    int p = b;
    for (; p + 4 <= e; p += 4) {                      // 4-way MLP
        float2 e0 = __ldg(&g_edge[p]);
        float2 e1 = __ldg(&g_edge[p + 1]);
        float2 e2 = __ldg(&g_edge[p + 2]);
        float2 e3 = __ldg(&g_edge[p + 3]);
        float2 h0 = __half22float2(hin2[(size_t)__float_as_int(e0.x) * 32 + lane]);
        float2 h1 = __half22float2(hin2[(size_t)__float_as_int(e1.x) * 32 + lane]);
        float2 h2 = __half22float2(hin2[(size_t)__float_as_int(e2.x) * 32 + lane]);
        float2 h3 = __half22float2(hin2[(size_t)__float_as_int(e3.x) * 32 + lane]);
        acc.x = fmaf(e0.y, h0.x, acc.x);
        acc.y = fmaf(e0.y, h0.y, acc.y);
        acc.x = fmaf(e1.y, h1.x, acc.x);
        acc.y = fmaf(e1.y, h1.y, acc.y);
        acc.x = fmaf(e2.y, h2.x, acc.x);
        acc.y = fmaf(e2.y, h2.y, acc.y);
        acc.x = fmaf(e3.y, h3.x, acc.x);
        acc.y = fmaf(e3.y, h3.y, acc.y);
    }
    for (; p < e; p++) {
        float2 ed = __ldg(&g_edge[p]);
        float2 hv = __half22float2(hin2[(size_t)__float_as_int(ed.x) * 32 + lane]);
        acc.x = fmaf(ed.y, hv.x, acc.x);
        acc.y = fmaf(ed.y, hv.y, acc.y);
    }
    hout2[(size_t)c * 32 + lane] = __floats2half2_rn(acc.x, acc.y);
}

// ---------------- final: out = log_softmax(sum_k temp[k] * h_k) -------------
__global__ __launch_bounds__(256) void k_final(const float* __restrict__ temp,
                                               float* __restrict__ out) {
    int t = blockIdx.x * blockDim.x + threadIdx.x;
    int c = t >> 5, lane = t & 31;
    if (c >= N_NODES) return;
    size_t idx = (size_t)c * 32 + lane;
    float2 s2 = make_float2(0.f, 0.f);
    #pragma unroll
    for (int k = 0; k <= KITER; k++) {
        float tk = __ldg(&temp[k]);
        float2 v = __half22float2(((const __half2*)(g_hk + (size_t)k * HSZ))[idx]);
        s2.x = fmaf(tk, v.x, s2.x);
        s2.y = fmaf(tk, v.y, s2.y);
    }
    float m = fmaxf(s2.x, s2.y);
    #pragma unroll
    for (int o = 16; o > 0; o >>= 1) m = fmaxf(m, __shfl_xor_sync(0xFFFFFFFFu, m, o));
    float s = expf(s2.x - m) + expf(s2.y - m);
    #pragma unroll
    for (int o = 16; o > 0; o >>= 1) s += __shfl_xor_sync(0xFFFFFFFFu, s, o);
    float ls = m + logf(s);
    ((float2*)out)[idx] = make_float2(s2.x - ls, s2.y - ls);
}

// ---------------- driver ----------------
extern "C" void kernel_launch(void* const* d_in, const int* in_sizes, int n_in,
                              void* d_out, int out_size) {
    const float* x    = (const float*)d_in[0];
    const void*  ei   = d_in[1];
    const float* W1   = (const float*)d_in[2];
    const float* b1   = (const float*)d_in[3];
    const float* W2   = (const float*)d_in[4];
    const float* b2   = (const float*)d_in[5];
    const float* temp = (const float*)d_in[6];
    float* out = (float*)d_out;

    // side stream + fork/join events, created once on the first (uncaptured)
    // correctness call; reused inside capture as a standard fork-join pattern.
    static cudaStream_t s2 = nullptr;
    static cudaEvent_t ev_fork = nullptr, ev_join = nullptr;
    if (s2 == nullptr) {
        cudaStreamCreateWithFlags(&s2, cudaStreamNonBlocking);
        cudaEventCreateWithFlags(&ev_fork, cudaEventDisableTiming);
        cudaEventCreateWithFlags(&ev_join, cudaEventDisableTiming);
    }
    cudaFuncSetAttribute(k_fused, cudaFuncAttributeMaxDynamicSharedMemorySize, SMEMF);

    // fork: graph preprocessing on s2, concurrent with weight split + MLP
    cudaEventRecord(ev_fork, 0);
    cudaStreamWaitEvent(s2, ev_fork, 0);
    k_init<<<NB, 256, 0, s2>>>();
    k_count<<<EB, 256, 0, s2>>>(ei);
    k_bsum<<<NB, 256, 0, s2>>>();
    k_scanb<<<1, 512, 0, s2>>>();
    k_offsets<<<NB, 256, 0, s2>>>();
    k_scatter<<<EB, 256, 0, s2>>>(ei);
    cudaEventRecord(ev_join, s2);

    // main stream: MLP chain
    k_split_w<<<(HIDDEN * 1024 + NCLASS * 512 + 255) / 256, 256>>>(W1, W2);
    k_fused<<<M_PAD / 128, 256, SMEMF>>>(x, b1, b2);

    // join: propagation needs both branches
    cudaStreamWaitEvent(0, ev_join, 0);

    const int prop_blocks = (N_NODES * 32 + 255) / 256;
    for (int k = 0; k < KITER; k++)
        k_prop<<<prop_blocks, 256>>>(k);

    k_final<<<prop_blocks, 256>>>(temp, out);
}